// round 14
// baseline (speedup 1.0000x reference)
#include <cuda_runtime.h>

#define NEGF  (-1e30f)
#define LOG2E (1.4426950408889634f)
#define LN2   (0.6931471805599453f)
#define MAXB  4096
#define NW    6
#define NT    (NW * 32)          // 192 threads
#define SMX   160                // slot count (max slot 151), padded
#define PMX   320                // pair count for final gather
#define EBIAS 100                // renorm target: warp max = 2^EBIAS

__device__ float g_loss[MAXB];
__device__ unsigned int g_ticket = 0;

__device__ __forceinline__ float ex2f_(float x){ float y; asm("ex2.approx.f32 %0,%1;":"=f"(y):"f"(x)); return y; }
__device__ __forceinline__ float lg2f_(float x){ float y; asm("lg2.approx.f32 %0,%1;":"=f"(y):"f"(x)); return y; }

__device__ __forceinline__ float lae2(float x, float y) {
    float m = fmaxf(x, y);
    float d = -fabsf(x - y);
    return m + lg2f_(1.0f + ex2f_(d));
}

// v * 2^d, exact power-of-2 factors, d clamped to [-252, 252]
__device__ __forceinline__ float ldx2(float v, int d) {
    d = d > 252 ? 252 : (d < -252 ? -252 : d);
    int d1 = d >> 1, d2 = d - d1;
    v *= __int_as_float((127 + d1) << 23);
    v *= __int_as_float((127 + d2) << 23);
    return v;
}

__device__ __forceinline__ void cp4(float* s, const float* g) {
    unsigned sa = (unsigned)__cvta_generic_to_shared(s);
    asm volatile("cp.async.ca.shared.global [%0], [%1], 4;" :: "r"(sa), "l"(g));
}
__device__ __forceinline__ void cp_commit() { asm volatile("cp.async.commit_group;"); }
__device__ __forceinline__ void cp_wait1()  { asm volatile("cp.async.wait_group 1;"); }

// Slot s = pairs (2s, 2s+1) = extended positions 4s..4s+3.  s = 24*warp + lane.
// Warps >=1: lanes 0-7 left halo (redundant), lanes 8-31 owned.
// Key property: the shfl'd value (a1B) is produced by a thread-LOCAL chain, so
// shfl latency is off the per-step recurrence (local cycle = FADD+FMAF+FMUL).
__global__ void __launch_bounds__(NT) ctc_fwd_kernel(
    const float* __restrict__ log_probs,   // [B, T, V]
    const int*   __restrict__ in_len,
    const int*   __restrict__ targets,     // [B, S]
    const int*   __restrict__ tgt_len,
    float* __restrict__ out,
    int T, int V, int S, int B)
{
    __shared__ float4 ss4[2 * SMX];        // per-slot state (a0A,a1A,a0B,a1B), dbl-buffered
    __shared__ float  stgl[2 * 8 * NT * 2];// staged label lp, [2][8][NT][2]
    __shared__ float  stgb[2 * 8 * NW];    // staged blank lp, per-warp copies
    __shared__ float  sf0[PMX], sf1[PMX];  // final per-pair alphas
    __shared__ int    sE[2 * NW];          // per-warp scale, dbl-buffered
    __shared__ int    sEf[NW];
    __shared__ unsigned int s_rank;

    const int b    = blockIdx.x;
    const int j    = threadIdx.x;
    const int warp = j >> 5;
    const int lane = j & 31;
    const int s    = 24 * warp + lane;     // slot
    const int pA   = 2 * s, pB = 2 * s + 1;
    const bool owned = (warp == 0) || (lane >= 8);

    int L = tgt_len[b]; if (L > S) L = S;
    int Tin = in_len[b];
    if (Tin > T) Tin = T;
    if (Tin < 1) Tin = 1;

    const float* lp = log_probs + (size_t)b * T * V;
    const int*   tg = targets   + (size_t)b * S;

    const bool actA  = (pA <= L), act1A = (pA < L);
    const bool actB  = (pB <= L), act1B = (pB < L);
    const bool wact  = (48 * warp) <= L;
    int labA = 0, labB = 0;
    float skA = 0.0f, skB = 0.0f;
    if (act1A) { labA = tg[pA]; skA = (pA >= 1 && labA != tg[pA - 1]) ? 1.0f : 0.0f; }
    if (act1B) { labB = tg[pB]; skB = (labB != tg[pB - 1]) ? 1.0f : 0.0f; }  // pB >= 1 always

    // zero-init shared state
    for (int i = j; i < 2 * SMX; i += NT) ss4[i] = make_float4(0.f, 0.f, 0.f, 0.f);
    for (int i = j; i < PMX; i += NT) { sf0[i] = 0.f; sf1[i] = 0.f; }
    if (j < 2 * NW) sE[j] = -EBIAS;
    __syncthreads();

    // t = 0 state (only slot 0 nonzero), scale E = -EBIAS
    float a0A = 0.f, a1A = 0.f, a0B = 0.f, a1B = 0.f;
    int   E   = -EBIAS;
    if (j == 0) {
        a0A = ex2f_(lp[0] * LOG2E + (float)EBIAS);
        if (L > 0) a1A = ex2f_(lp[labA] * LOG2E + (float)EBIAS);
        ss4[0] = make_float4(a0A, a1A, 0.f, 0.f);
    }

    // prologue: stage t=1..8 -> buf0, t=9..16 -> buf1
    #pragma unroll
    for (int g = 0; g < 2; ++g) {
        #pragma unroll
        for (int k = 0; k < 8; ++k) {
            int t = 1 + g * 8 + k;
            if (t < Tin) {
                float* base = &stgl[(((g * 8 + k) * NT) + j) * 2];
                if (act1A) cp4(base + 0, lp + (size_t)t * V + labA);
                if (act1B) cp4(base + 1, lp + (size_t)t * V + labB);
            }
        }
        if (wact && lane >= 24) {
            int k = lane - 24, t = 1 + g * 8 + k;
            if (t < Tin) cp4(&stgb[(g * 8 + k) * NW + warp], lp + (size_t)t * V);
        }
        cp_commit();
    }

    int cur = 0;
    for (int tb = 1; tb < Tin; tb += 8, cur ^= 1) {
        cp_wait1();
        __syncthreads();                   // stage[cur] + ss4[cur] + sE[cur] visible

        if (wact) {
            // halo refresh candidates at scale Eh
            const int En = (warp > 0) ? sE[cur * NW + (warp - 1)] : E;
            float h0A = a0A, h1A = a1A, h0B = a0B, h1B = a1B;
            int   Eh  = E;
            if (!owned) {
                float4 v = ss4[cur * SMX + s];
                h0A = v.x; h1A = v.y; h0B = v.z; h1B = v.w;
                Eh = En;
            }

            // joint renorm in exponent domain: warp max -> exactly 2^EBIAS
            int ie = -0x40000000;
            if (h0A > 0.f) { int e = ((__float_as_int(h0A) >> 23) & 255) + Eh; ie = ie > e ? ie : e; }
            if (h1A > 0.f) { int e = ((__float_as_int(h1A) >> 23) & 255) + Eh; ie = ie > e ? ie : e; }
            if (h0B > 0.f) { int e = ((__float_as_int(h0B) >> 23) & 255) + Eh; ie = ie > e ? ie : e; }
            if (h1B > 0.f) { int e = ((__float_as_int(h1B) >> 23) & 255) + Eh; ie = ie > e ? ie : e; }
            ie = __reduce_max_sync(0xffffffffu, ie);
            if (ie > -0x20000000) {
                const int Enew = (ie - 127) - EBIAS;
                const int d = Eh - Enew;   // bounded: no overflow possible
                a0A = ldx2(h0A, d); a1A = ldx2(h1A, d);
                a0B = ldx2(h0B, d); a1B = ldx2(h1B, d);
                E = Enew;
            }

            // staged log-probs -> linear registers (ALL before refills: no WAR)
            float plA[8], plB[8], pb[8];
            #pragma unroll
            for (int k = 0; k < 8; ++k) {
                pb[k] = ex2f_(stgb[(cur * 8 + k) * NW + warp] * LOG2E);
                float2 v = *reinterpret_cast<const float2*>(&stgl[(((cur * 8 + k) * NT) + j) * 2]);
                plA[k] = ex2f_(v.x * LOG2E);
                plB[k] = ex2f_(v.y * LOG2E);
            }

            // refill stage[cur] for t = tb+16..tb+23 (self/warp-owned slots)
            #pragma unroll
            for (int k = 0; k < 8; ++k) {
                int tn = tb + 16 + k;
                if (tn < Tin) {
                    float* base = &stgl[(((cur * 8 + k) * NT) + j) * 2];
                    if (act1A) cp4(base + 0, lp + (size_t)tn * V + labA);
                    if (act1B) cp4(base + 1, lp + (size_t)tn * V + labB);
                }
            }
            if (lane >= 24) {
                int k = lane - 24, tn = tb + 16 + k;
                if (tn < Tin) cp4(&stgb[(cur * 8 + k) * NW + warp], lp + (size_t)tn * V);
            }

            int rem = Tin - tb; if (rem > 8) rem = 8;
            const int rA0 = actA  ? rem : 0;
            const int rA1 = act1A ? rem : 0;
            const int rB0 = actB  ? rem : 0;
            const int rB1 = act1B ? rem : 0;

            // ---- 8 steps; shfl feeds only A-pair (off the local recurrence) ----
            #pragma unroll
            for (int k = 0; k < 8; ++k) {
                float o = __shfl_up_sync(0xffffffffu, a1B, 1);
                o = (lane == 0) ? 0.0f : o;
                float n0A = (a0A + o) * pb[k];
                float n1A = fmaf(skA, o, a1A + a0A) * plA[k];
                float n0B = (a0B + a1A) * pb[k];                 // old a1A
                float n1B = fmaf(skB, a1A, a1B + a0B) * plB[k];  // old a1A
                a0A = (k < rA0) ? n0A : a0A;
                a1A = (k < rA1) ? n1A : a1A;
                a0B = (k < rB0) ? n0B : a0B;
                a1B = (k < rB1) ? n1B : a1B;
            }
        }
        cp_commit();                       // uniform; closes this superstep's refills

        const int nxt = cur ^ 1;
        if (owned) ss4[nxt * SMX + s] = make_float4(a0A, a1A, a0B, a1B);
        if (lane == 0) sE[nxt * NW + warp] = E;
    }

    // epilogue: publish final per-pair alphas + per-warp scales
    __syncthreads();
    if (owned) {
        sf0[pA] = a0A; sf1[pA] = a1A;
        sf0[pB] = a0B; sf1[pB] = a1B;
    }
    if (lane == 0) sEf[warp] = E;
    __syncthreads();
    if (j == 0) {
        // owner warp of slot q: warp 0 owns 0..31; warp w>=1 owns 24w+8..24w+31
        int sx = L >> 1;
        int wx = (sx <= 31) ? 0 : (sx - 8) / 24;
        float v0 = sf0[L];
        float x = (v0 > 0.f) ? (lg2f_(v0) + (float)sEf[wx]) : NEGF;
        float y = NEGF;
        if (L > 0) {
            int q = L - 1, sy = q >> 1;
            int wy = (sy <= 31) ? 0 : (sy - 8) / 24;
            float v1 = sf1[q];
            if (v1 > 0.f) y = lg2f_(v1) + (float)sEf[wy];
        }
        float ll2 = lae2(x, y);
        float loss = -ll2 * LN2;
        if (!(loss <= 1e29f)) loss = 0.0f;         // zero_infinity (+ nan/inf guard)
        int Lm = (L > 0) ? L : 1;
        g_loss[b] = loss / (float)Lm;
    }

    // fused deterministic reduction: last block sums in fixed order
    __threadfence();
    __syncthreads();
    if (j == 0) s_rank = atomicAdd(&g_ticket, 1u);
    __syncthreads();
    if (s_rank == (unsigned)(gridDim.x - 1)) {
        if (warp == 0) {
            float sum = 0.0f;
            for (int i = lane; i < B; i += 32) sum += g_loss[i];
            #pragma unroll
            for (int off = 16; off; off >>= 1)
                sum += __shfl_xor_sync(0xffffffffu, sum, off);
            if (lane == 0) {
                out[0] = sum / (float)B;
                g_ticket = 0;              // reset for next graph replay
            }
        }
    }
}

extern "C" void kernel_launch(void* const* d_in, const int* in_sizes, int n_in,
                              void* d_out, int out_size) {
    const float* log_probs = (const float*)d_in[0];
    const int*   in_len    = (const int*)d_in[1];
    const int*   targets   = (const int*)d_in[2];
    const int*   tgt_len   = (const int*)d_in[3];

    const int B = in_sizes[1];
    const int S = in_sizes[2] / B;
    const int V = 128;
    const int T = in_sizes[0] / (B * V);

    ctc_fwd_kernel<<<B, NT>>>(log_probs, in_len, targets, tgt_len,
                              (float*)d_out, T, V, S, B);
}

// round 15
// speedup vs baseline: 1.1190x; 1.1190x over previous
#include <cuda_runtime.h>

#define NEGF  (-1e30f)
#define LOG2E (1.4426950408889634f)
#define LN2   (0.6931471805599453f)
#define MAXB  4096
#define NW    11
#define NT    (NW * 32)          // 352 threads
#define PMAX  272
#define EBIAS 100                // renorm target: warp max = 2^EBIAS

__device__ float g_loss[MAXB];
__device__ unsigned int g_ticket = 0;

__device__ __forceinline__ float ex2f_(float x){ float y; asm("ex2.approx.f32 %0,%1;":"=f"(y):"f"(x)); return y; }
__device__ __forceinline__ float lg2f_(float x){ float y; asm("lg2.approx.f32 %0,%1;":"=f"(y):"f"(x)); return y; }

__device__ __forceinline__ float lae2(float x, float y) {
    float m = fmaxf(x, y);
    float d = -fabsf(x - y);
    return m + lg2f_(1.0f + ex2f_(d));
}

// v * 2^d, exact power-of-2 factors, d clamped to [-252, 252]
__device__ __forceinline__ float ldx2(float v, int d) {
    d = d > 252 ? 252 : (d < -252 ? -252 : d);
    int d1 = d >> 1, d2 = d - d1;
    v *= __int_as_float((127 + d1) << 23);
    v *= __int_as_float((127 + d2) << 23);
    return v;
}

// Pair p = (2p blank, 2p+1 label tg[p]).  p = 24*warp + lane.
// Warps >=1: lanes 0-7 left halo (redundant), lanes 8-31 owned.
// Alphas LINEAR at per-warp scale E; superstep-start joint renorm in the
// exponent domain (overflow-free).  Log-probs prefetched one full superstep
// ahead in REGISTER rings (LDG), blank conversion shared across the warp.
__global__ void __launch_bounds__(NT) ctc_fwd_kernel(
    const float* __restrict__ log_probs,   // [B, T, V]
    const int*   __restrict__ in_len,
    const int*   __restrict__ targets,     // [B, S]
    const int*   __restrict__ tgt_len,
    float* __restrict__ out,
    int T, int V, int S, int B)
{
    __shared__ float sa0[2 * PMAX];
    __shared__ float sa1[2 * PMAX];
    __shared__ int   sE[2 * NW];           // per-warp scale, double buffered
    __shared__ int   sEf[NW];              // final scales
    __shared__ unsigned int s_rank;

    const int b    = blockIdx.x;
    const int j    = threadIdx.x;
    const int warp = j >> 5;
    const int lane = j & 31;
    const int p    = 24 * warp + lane;
    const bool owned = (warp == 0) || (lane >= 8);

    int L = tgt_len[b]; if (L > S) L = S;
    int Tin = in_len[b];
    if (Tin > T) Tin = T;
    if (Tin < 1) Tin = 1;

    const float* lp = log_probs + (size_t)b * T * V;
    const int*   tg = targets   + (size_t)b * S;

    const bool act  = (p <= L);
    const bool act1 = (p <  L);
    const bool wact = (24 * warp) <= L;
    int   lab = 0;
    float skf = 0.0f;
    if (act1) {
        lab = tg[p];
        skf = (p >= 1 && lab != tg[p - 1]) ? 1.0f : 0.0f;
    }

    // t = 0: linear alphas at scale E = -EBIAS (max ~= 2^EBIAS)
    float la0 = 0.0f, la1 = 0.0f;
    int   E   = -EBIAS;
    if (p == 0) {
        la0 = ex2f_(lp[0] * LOG2E + (float)EBIAS);
        if (L > 0) la1 = ex2f_(lp[lab] * LOG2E + (float)EBIAS);
    }
    if (owned) { sa0[p] = la0; sa1[p] = la1; }
    if (lane == 0) sE[warp] = E;

    // prologue: register rings for t = 1..8
    float ringl[8];
    float blr = 0.0f;
    #pragma unroll
    for (int k = 0; k < 8; ++k) {
        int t = 1 + k;
        ringl[k] = (act1 && t < T) ? lp[(size_t)t * V + lab] : 0.0f;
    }
    if (wact && lane < 8) {
        int t = 1 + lane;
        if (t < T) blr = lp[(size_t)t * V];
    }

    int cur = 0;
    for (int tb = 1; tb < Tin; tb += 8, cur ^= 1) {
        __syncthreads();                   // sa[cur] + sE[cur] visible

        if (wact) {
            // halo refresh: candidate values at scale Eh
            const int En = (warp > 0) ? sE[cur * NW + (warp - 1)] : E;
            float h0 = la0, h1 = la1;
            int   Eh = E;
            if (!owned) {
                h0 = sa0[cur * PMAX + p];
                h1 = sa1[cur * PMAX + p];
                Eh = En;
            }

            // joint renorm in exponent domain: warp max -> exactly 2^EBIAS
            int ie = -0x40000000;
            if (h0 > 0.0f) { int e0 = ((__float_as_int(h0) >> 23) & 255) + Eh; ie = ie > e0 ? ie : e0; }
            if (h1 > 0.0f) { int e1 = ((__float_as_int(h1) >> 23) & 255) + Eh; ie = ie > e1 ? ie : e1; }
            ie = __reduce_max_sync(0xffffffffu, ie);
            if (ie > -0x20000000) {        // some mass in warp
                const int Enew = (ie - 127) - EBIAS;
                la0 = ldx2(h0, Eh - Enew); // shift bounded: no overflow possible
                la1 = ldx2(h1, Eh - Enew);
                E = Enew;
            }

            // blank conversion: one ex2 per warp-slot, broadcast via shfl
            float bv = 0.0f;
            if (lane < 8) bv = ex2f_(blr * LOG2E);
            float pb[8], pl[8];
            #pragma unroll
            for (int k = 0; k < 8; ++k) pb[k] = __shfl_sync(0xffffffffu, bv, k);
            // label conversion: registers only
            #pragma unroll
            for (int k = 0; k < 8; ++k) pl[k] = ex2f_(ringl[k] * LOG2E);

            // prefetch next superstep (t = tb+8..tb+15) into rings
            if (act1) {
                #pragma unroll
                for (int k = 0; k < 8; ++k) {
                    int tn = tb + 8 + k;
                    if (tn < T) ringl[k] = lp[(size_t)tn * V + lab];
                }
            }
            if (lane < 8) {
                int tn = tb + 8 + lane;
                if (tn < T) blr = lp[(size_t)tn * V];
            }

            int rem = Tin - tb; if (rem > 8) rem = 8;
            const int rem0 = act  ? rem : 0;
            const int rem1 = act1 ? rem : 0;

            // ---- 8 steps: pure shfl + FMA, zero MUFU on the chain ----
            #pragma unroll
            for (int k = 0; k < 8; ++k) {
                float o = __shfl_up_sync(0xffffffffu, la1, 1);
                o = (lane == 0) ? 0.0f : o;
                float base = la1 + la0;
                float n1 = fmaf(skf, o, base) * pl[k];
                float n0 = (la0 + o) * pb[k];
                la0 = (k < rem0) ? n0 : la0;
                la1 = (k < rem1) ? n1 : la1;
            }
        }

        const int nxt = cur ^ 1;
        if (owned) { sa0[nxt * PMAX + p] = la0; sa1[nxt * PMAX + p] = la1; }
        if (lane == 0) sE[nxt * NW + warp] = E;
    }

    // epilogue: per-batch loss
    __syncthreads();
    if (owned) { sa0[p] = la0; sa1[p] = la1; }
    if (lane == 0) sEf[warp] = E;
    __syncthreads();
    if (j == 0) {
        // owner warp of pair q: warp 0 owns 0..31; warp w>=1 owns 24w+8..24w+31
        int wx = (L <= 31) ? 0 : (L - 8) / 24;
        float v0 = sa0[L];
        float x = (v0 > 0.0f) ? (lg2f_(v0) + (float)sEf[wx]) : NEGF;
        float y = NEGF;
        if (L > 0) {
            int q = L - 1;
            int wy = (q <= 31) ? 0 : (q - 8) / 24;
            float v1 = sa1[q];
            if (v1 > 0.0f) y = lg2f_(v1) + (float)sEf[wy];
        }
        float ll2 = lae2(x, y);
        float loss = -ll2 * LN2;
        if (!(loss <= 1e29f)) loss = 0.0f;         // zero_infinity (+ nan/inf guard)
        int Lm = (L > 0) ? L : 1;
        g_loss[b] = loss / (float)Lm;
    }

    // fused deterministic reduction: last block sums in fixed order
    __threadfence();
    __syncthreads();
    if (j == 0) s_rank = atomicAdd(&g_ticket, 1u);
    __syncthreads();
    if (s_rank == (unsigned)(gridDim.x - 1)) {
        if (warp == 0) {
            float s = 0.0f;
            for (int i = lane; i < B; i += 32) s += g_loss[i];
            #pragma unroll
            for (int off = 16; off; off >>= 1)
                s += __shfl_xor_sync(0xffffffffu, s, off);
            if (lane == 0) {
                out[0] = s / (float)B;
                g_ticket = 0;              // reset for next graph replay
            }
        }
    }
}

extern "C" void kernel_launch(void* const* d_in, const int* in_sizes, int n_in,
                              void* d_out, int out_size) {
    const float* log_probs = (const float*)d_in[0];
    const int*   in_len    = (const int*)d_in[1];
    const int*   targets   = (const int*)d_in[2];
    const int*   tgt_len   = (const int*)d_in[3];

    const int B = in_sizes[1];
    const int S = in_sizes[2] / B;
    const int V = 128;
    const int T = in_sizes[0] / (B * V);

    ctc_fwd_kernel<<<B, NT>>>(log_probs, in_len, targets, tgt_len,
                              (float*)d_out, T, V, S, B);
}

// round 16
// speedup vs baseline: 1.2653x; 1.1307x over previous
#include <cuda_runtime.h>

#define NEGF  (-1e30f)
#define LOG2E (1.4426950408889634f)
#define LN2   (0.6931471805599453f)
#define MAXB  4096
#define NW    11
#define NT    (NW * 32)          // 352 threads
#define PMAX  272
#define EBIAS 100                // renorm target: warp max = 2^EBIAS

__device__ float g_loss[MAXB];
__device__ unsigned int g_ticket = 0;

__device__ __forceinline__ float ex2f_(float x){ float y; asm("ex2.approx.f32 %0,%1;":"=f"(y):"f"(x)); return y; }
__device__ __forceinline__ float lg2f_(float x){ float y; asm("lg2.approx.f32 %0,%1;":"=f"(y):"f"(x)); return y; }

__device__ __forceinline__ float lae2(float x, float y) {
    float m = fmaxf(x, y);
    float d = -fabsf(x - y);
    return m + lg2f_(1.0f + ex2f_(d));
}

// v * 2^d, exact power-of-2 factors, d clamped to [-252, 252]
__device__ __forceinline__ float ldx2(float v, int d) {
    d = d > 252 ? 252 : (d < -252 ? -252 : d);
    int d1 = d >> 1, d2 = d - d1;
    v *= __int_as_float((127 + d1) << 23);
    v *= __int_as_float((127 + d2) << 23);
    return v;
}

__device__ __forceinline__ void cp4(float* s, const float* g) {
    unsigned sa = (unsigned)__cvta_generic_to_shared(s);
    asm volatile("cp.async.ca.shared.global [%0], [%1], 4;" :: "r"(sa), "l"(g));
}
__device__ __forceinline__ void cp_commit() { asm volatile("cp.async.commit_group;"); }
__device__ __forceinline__ void cp_wait1()  { asm volatile("cp.async.wait_group 1;"); }

// Pair p = (2p blank, 2p+1 label tg[p]).  p = 24*warp + lane.
// Warps >=1: lanes 0-7 left halo (redundant), lanes 8-31 owned.
// Alphas LINEAR at per-warp scale E (actual = la * 2^E); superstep-start joint
// renorm in the exponent domain (overflow-free, 249-bit tail window).
// Blank conversion shared across the warp (lanes 0-7 + shfl broadcast).
__global__ void __launch_bounds__(NT) ctc_fwd_kernel(
    const float* __restrict__ log_probs,   // [B, T, V]
    const int*   __restrict__ in_len,
    const int*   __restrict__ targets,     // [B, S]
    const int*   __restrict__ tgt_len,
    float* __restrict__ out,
    int T, int V, int S, int B)
{
    __shared__ float sa0[2 * PMAX];
    __shared__ float sa1[2 * PMAX];
    __shared__ float stgl[16 * NT];        // [2][8][NT] thread-private slots
    __shared__ float stgb[16 * NW];        // [2][8][NW] warp-private blank slots
    __shared__ int   sE[2 * NW];           // per-warp scale, double buffered
    __shared__ int   sEf[NW];              // final scales
    __shared__ unsigned int s_rank;

    const int b    = blockIdx.x;
    const int j    = threadIdx.x;
    const int warp = j >> 5;
    const int lane = j & 31;
    const int p    = 24 * warp + lane;
    const bool owned = (warp == 0) || (lane >= 8);

    int L = tgt_len[b]; if (L > S) L = S;
    int Tin = in_len[b];
    if (Tin > T) Tin = T;
    if (Tin < 1) Tin = 1;

    const float* lp = log_probs + (size_t)b * T * V;
    const int*   tg = targets   + (size_t)b * S;

    const bool act  = (p <= L);
    const bool act1 = (p <  L);
    const bool wact = (24 * warp) <= L;
    int   lab = 0;
    float skf = 0.0f;
    if (act1) {
        lab = tg[p];
        skf = (p >= 1 && lab != tg[p - 1]) ? 1.0f : 0.0f;
    }

    // t = 0: linear alphas at scale E = -EBIAS (max ~= 2^EBIAS)
    float la0 = 0.0f, la1 = 0.0f;
    int   E   = -EBIAS;
    if (p == 0) {
        la0 = ex2f_(lp[0] * LOG2E + (float)EBIAS);
        if (L > 0) la1 = ex2f_(lp[lab] * LOG2E + (float)EBIAS);
    }
    if (owned) { sa0[p] = la0; sa1[p] = la1; }
    if (lane == 0) sE[warp] = E;

    // prologue: stage t=1..8 -> buf0, t=9..16 -> buf1
    if (act) {
        #pragma unroll
        for (int k = 0; k < 8; ++k) { int t = 1 + k; if (t < Tin) cp4(&stgl[k * NT + j], lp + (size_t)t * V + lab); }
    }
    if (wact && lane >= 24) { int k = lane - 24, t = 1 + k; if (t < Tin) cp4(&stgb[k * NW + warp], lp + (size_t)t * V); }
    cp_commit();
    if (act) {
        #pragma unroll
        for (int k = 0; k < 8; ++k) { int t = 9 + k; if (t < Tin) cp4(&stgl[(8 + k) * NT + j], lp + (size_t)t * V + lab); }
    }
    if (wact && lane >= 24) { int k = lane - 24, t = 9 + k; if (t < Tin) cp4(&stgb[(8 + k) * NW + warp], lp + (size_t)t * V); }
    cp_commit();

    int cur = 0;
    for (int tb = 1; tb < Tin; tb += 8, cur ^= 1) {
        cp_wait1();
        __syncthreads();                   // stage[cur] + sa[cur] + sE[cur] visible

        if (wact) {
            // halo refresh: candidate values at scale Eh
            const int En = (warp > 0) ? sE[cur * NW + (warp - 1)] : E;
            float h0 = la0, h1 = la1;
            int   Eh = E;
            if (!owned) {
                h0 = sa0[cur * PMAX + p];
                h1 = sa1[cur * PMAX + p];
                Eh = En;
            }

            // joint renorm in exponent domain: warp max -> exactly 2^EBIAS
            int ie = -0x40000000;
            if (h0 > 0.0f) { int e0 = ((__float_as_int(h0) >> 23) & 255) + Eh; ie = ie > e0 ? ie : e0; }
            if (h1 > 0.0f) { int e1 = ((__float_as_int(h1) >> 23) & 255) + Eh; ie = ie > e1 ? ie : e1; }
            ie = __reduce_max_sync(0xffffffffu, ie);
            if (ie > -0x20000000) {        // some mass in warp
                const int Enew = (ie - 127) - EBIAS;
                la0 = ldx2(h0, Eh - Enew); // shift bounded: no overflow possible
                la1 = ldx2(h1, Eh - Enew);
                E = Enew;
            }

            // blank conversion shared: lanes 0-7 convert one slot each,
            // broadcast via shfl (same bits -> same ex2 result as before)
            float bv = 0.0f;
            if (lane < 8) bv = ex2f_(stgb[(cur * 8 + lane) * NW + warp] * LOG2E);
            float pb[8], pl[8];
            #pragma unroll
            for (int k = 0; k < 8; ++k) pb[k] = __shfl_sync(0xffffffffu, bv, k);
            // label conversion: own slots (ALL reads before refills: no WAR)
            #pragma unroll
            for (int k = 0; k < 8; ++k) pl[k] = ex2f_(stgl[(cur * 8 + k) * NT + j] * LOG2E);

            // refill stage[cur] for t = tb+16..tb+23 (self-owned slots)
            if (act) {
                #pragma unroll
                for (int k = 0; k < 8; ++k) { int tn = tb + 16 + k; if (tn < Tin) cp4(&stgl[(cur * 8 + k) * NT + j], lp + (size_t)tn * V + lab); }
            }
            if (lane >= 24) { int k = lane - 24, tn = tb + 16 + k; if (tn < Tin) cp4(&stgb[(cur * 8 + k) * NW + warp], lp + (size_t)tn * V); }

            int rem = Tin - tb; if (rem > 8) rem = 8;
            const int rem0 = act  ? rem : 0;
            const int rem1 = act1 ? rem : 0;

            // ---- 8 steps: pure shfl + FMA, zero MUFU on the chain ----
            #pragma unroll
            for (int k = 0; k < 8; ++k) {
                float o = __shfl_up_sync(0xffffffffu, la1, 1);
                o = (lane == 0) ? 0.0f : o;
                float base = la1 + la0;
                float n1 = fmaf(skf, o, base) * pl[k];
                float n0 = (la0 + o) * pb[k];
                la0 = (k < rem0) ? n0 : la0;
                la1 = (k < rem1) ? n1 : la1;
            }
        }
        cp_commit();                       // uniform; pairs with refills above

        const int nxt = cur ^ 1;
        if (owned) { sa0[nxt * PMAX + p] = la0; sa1[nxt * PMAX + p] = la1; }
        if (lane == 0) sE[nxt * NW + warp] = E;
    }

    // epilogue: per-batch loss
    __syncthreads();
    if (owned) { sa0[p] = la0; sa1[p] = la1; }
    if (lane == 0) sEf[warp] = E;
    __syncthreads();
    if (j == 0) {
        // owner warp of pair q: warp 0 owns 0..31; warp w>=1 owns 24w+8..24w+31
        int wx = (L <= 31) ? 0 : (L - 8) / 24;
        float v0 = sa0[L];
        float x = (v0 > 0.0f) ? (lg2f_(v0) + (float)sEf[wx]) : NEGF;
        float y = NEGF;
        if (L > 0) {
            int q = L - 1;
            int wy = (q <= 31) ? 0 : (q - 8) / 24;
            float v1 = sa1[q];
            if (v1 > 0.0f) y = lg2f_(v1) + (float)sEf[wy];
        }
        float ll2 = lae2(x, y);
        float loss = -ll2 * LN2;
        if (!(loss <= 1e29f)) loss = 0.0f;         // zero_infinity (+ nan/inf guard)
        int Lm = (L > 0) ? L : 1;
        g_loss[b] = loss / (float)Lm;
    }

    // fused deterministic reduction: last block sums in fixed order
    __threadfence();
    __syncthreads();
    if (j == 0) s_rank = atomicAdd(&g_ticket, 1u);
    __syncthreads();
    if (s_rank == (unsigned)(gridDim.x - 1)) {
        if (warp == 0) {
            float s = 0.0f;
            for (int i = lane; i < B; i += 32) s += g_loss[i];
            #pragma unroll
            for (int off = 16; off; off >>= 1)
                s += __shfl_xor_sync(0xffffffffu, s, off);
            if (lane == 0) {
                out[0] = s / (float)B;
                g_ticket = 0;              // reset for next graph replay
            }
        }
    }
}

extern "C" void kernel_launch(void* const* d_in, const int* in_sizes, int n_in,
                              void* d_out, int out_size) {
    const float* log_probs = (const float*)d_in[0];
    const int*   in_len    = (const int*)d_in[1];
    const int*   targets   = (const int*)d_in[2];
    const int*   tgt_len   = (const int*)d_in[3];

    const int B = in_sizes[1];
    const int S = in_sizes[2] / B;
    const int V = 128;
    const int T = in_sizes[0] / (B * V);

    ctc_fwd_kernel<<<B, NT>>>(log_probs, in_len, targets, tgt_len,
                              (float*)d_out, T, V, S, B);
}

// round 17
// speedup vs baseline: 1.3582x; 1.0734x over previous
#include <cuda_runtime.h>

#define NEGF  (-1e30f)
#define LOG2E (1.4426950408889634f)
#define LN2   (0.6931471805599453f)
#define MAXB  4096
#define NW    16
#define NT    (NW * 32)          // 512 threads
#define SMX   272                // slots 0..271 (need <= 256)
#define PMAX  272
#define EBIAS 96                 // renorm target: warp max = 2^EBIAS (31-bit headroom > 16*log2(3))

__device__ float g_loss[MAXB];
__device__ unsigned int g_ticket = 0;

__device__ __forceinline__ float ex2f_(float x){ float y; asm("ex2.approx.f32 %0,%1;":"=f"(y):"f"(x)); return y; }
__device__ __forceinline__ float lg2f_(float x){ float y; asm("lg2.approx.f32 %0,%1;":"=f"(y):"f"(x)); return y; }

__device__ __forceinline__ float lae2(float x, float y) {
    float m = fmaxf(x, y);
    float d = -fabsf(x - y);
    return m + lg2f_(1.0f + ex2f_(d));
}

// v * 2^d, exact power-of-2 factors, d clamped to [-252, 252]
__device__ __forceinline__ float ldx2(float v, int d) {
    d = d > 252 ? 252 : (d < -252 ? -252 : d);
    int d1 = d >> 1, d2 = d - d1;
    v *= __int_as_float((127 + d1) << 23);
    v *= __int_as_float((127 + d2) << 23);
    return v;
}

__device__ __forceinline__ void cp4(float* s, const float* g) {
    unsigned sa = (unsigned)__cvta_generic_to_shared(s);
    asm volatile("cp.async.ca.shared.global [%0], [%1], 4;" :: "r"(sa), "l"(g));
}
__device__ __forceinline__ void cp_commit() { asm volatile("cp.async.commit_group;"); }
__device__ __forceinline__ void cp_wait1()  { asm volatile("cp.async.wait_group 1;"); }

// Slot (= pair) s = positions (2s blank, 2s+1 label tg[s]).  s = 16*warp + lane.
// Warps >=1: lanes 0-15 left halo (redundant), lanes 16-31 owned -> 16
// autonomous steps per barrier.  Stage is indexed BY SLOT (owners write via
// cp.async; halo lanes read the owner's slot); a second uniform barrier
// orders all stage reads before refills (kills the WAR structurally).
__global__ void __launch_bounds__(NT) ctc_fwd_kernel(
    const float* __restrict__ log_probs,   // [B, T, V]
    const int*   __restrict__ in_len,
    const int*   __restrict__ targets,     // [B, S]
    const int*   __restrict__ tgt_len,
    float* __restrict__ out,
    int T, int V, int S, int B)
{
    __shared__ float sa0[2 * PMAX];
    __shared__ float sa1[2 * PMAX];
    __shared__ float stgl[2 * 16 * SMX];   // [2][16][SMX] slot-indexed label stage
    __shared__ float stgb[2 * 16 * NW];    // [2][16][NW] warp-private blank stage
    __shared__ int   sE[2 * NW];           // per-warp scale, double buffered
    __shared__ int   sEf[NW];              // final scales
    __shared__ unsigned int s_rank;

    const int b    = blockIdx.x;
    const int j    = threadIdx.x;
    const int warp = j >> 5;
    const int lane = j & 31;
    const int s    = 16 * warp + lane;     // slot = pair index
    const bool owned = (warp == 0) || (lane >= 16);

    int L = tgt_len[b]; if (L > S) L = S;
    int Tin = in_len[b];
    if (Tin > T) Tin = T;
    if (Tin < 1) Tin = 1;

    const float* lp = log_probs + (size_t)b * T * V;
    const int*   tg = targets   + (size_t)b * S;

    const bool act  = (s <= L);
    const bool act1 = (s <  L);
    const bool wact = (16 * warp) <= L;
    int   lab = 0;
    float skf = 0.0f;
    if (act1) {
        lab = tg[s];
        skf = (s >= 1 && lab != tg[s - 1]) ? 1.0f : 0.0f;
    }

    // t = 0: linear alphas at scale E = -EBIAS (max ~= 2^EBIAS)
    float la0 = 0.0f, la1 = 0.0f;
    int   E   = -EBIAS;
    if (s == 0) {
        la0 = ex2f_(lp[0] * LOG2E + (float)EBIAS);
        if (L > 0) la1 = ex2f_(lp[lab] * LOG2E + (float)EBIAS);
    }
    if (owned) { sa0[s] = la0; sa1[s] = la1; }
    if (lane == 0) sE[warp] = E;

    // prologue: stage t=1..16 -> buf0, t=17..32 -> buf1 (owners only)
    #pragma unroll
    for (int g = 0; g < 2; ++g) {
        if (owned && act1) {
            #pragma unroll
            for (int k = 0; k < 16; ++k) {
                int t = 1 + g * 16 + k;
                if (t < Tin) cp4(&stgl[(g * 16 + k) * SMX + s], lp + (size_t)t * V + lab);
            }
        }
        if (wact && lane >= 16) {
            int k = lane - 16, t = 1 + g * 16 + k;
            if (t < Tin) cp4(&stgb[(g * 16 + k) * NW + warp], lp + (size_t)t * V);
        }
        cp_commit();
    }

    int cur = 0;
    for (int tb = 1; tb < Tin; tb += 16, cur ^= 1) {
        cp_wait1();
        __syncthreads();                   // A: stage[cur] + sa[cur] + sE[cur] visible

        float pl[16], pb[16];
        if (wact) {
            // halo refresh: candidate values at scale Eh
            const int En = (warp > 0) ? sE[cur * NW + (warp - 1)] : E;
            float h0 = la0, h1 = la1;
            int   Eh = E;
            if (!owned) {
                h0 = sa0[cur * PMAX + s];
                h1 = sa1[cur * PMAX + s];
                Eh = En;
            }

            // joint renorm in exponent domain: warp max -> exactly 2^EBIAS
            int ie = -0x40000000;
            if (h0 > 0.0f) { int e0 = ((__float_as_int(h0) >> 23) & 255) + Eh; ie = ie > e0 ? ie : e0; }
            if (h1 > 0.0f) { int e1 = ((__float_as_int(h1) >> 23) & 255) + Eh; ie = ie > e1 ? ie : e1; }
            ie = __reduce_max_sync(0xffffffffu, ie);
            if (ie > -0x20000000) {        // some mass in warp
                const int Enew = (ie - 127) - EBIAS;
                la0 = ldx2(h0, Eh - Enew); // shift bounded: no overflow possible
                la1 = ldx2(h1, Eh - Enew);
                E = Enew;
            }

            // blank conversion shared: lanes 0-15 convert one slot each
            float bv = 0.0f;
            if (lane < 16) bv = ex2f_(stgb[(cur * 16 + lane) * NW + warp] * LOG2E);
            #pragma unroll
            for (int k = 0; k < 16; ++k) pb[k] = __shfl_sync(0xffffffffu, bv, k);
            // label conversion: slot-indexed reads (garbage for !act1 / tails
            // is discarded by the rem selects below — never enters live state)
            #pragma unroll
            for (int k = 0; k < 16; ++k) pl[k] = ex2f_(stgl[(cur * 16 + k) * SMX + s] * LOG2E);
        }
        __syncthreads();                   // B: ALL stage[cur] reads done before refills

        if (wact) {
            // refill stage[cur] for t = tb+32..tb+47 (owners only)
            if (owned && act1) {
                #pragma unroll
                for (int k = 0; k < 16; ++k) {
                    int tn = tb + 32 + k;
                    if (tn < Tin) cp4(&stgl[(cur * 16 + k) * SMX + s], lp + (size_t)tn * V + lab);
                }
            }
            if (lane >= 16) {
                int k = lane - 16, tn = tb + 32 + k;
                if (tn < Tin) cp4(&stgb[(cur * 16 + k) * NW + warp], lp + (size_t)tn * V);
            }

            int rem = Tin - tb; if (rem > 16) rem = 16;
            const int rem0 = act  ? rem : 0;
            const int rem1 = act1 ? rem : 0;

            // ---- 16 steps: pure shfl + FMA, zero MUFU on the chain ----
            #pragma unroll
            for (int k = 0; k < 16; ++k) {
                float o = __shfl_up_sync(0xffffffffu, la1, 1);
                o = (lane == 0) ? 0.0f : o;
                float base = la1 + la0;
                float n1 = fmaf(skf, o, base) * pl[k];
                float n0 = (la0 + o) * pb[k];
                la0 = (k < rem0) ? n0 : la0;
                la1 = (k < rem1) ? n1 : la1;
            }
        }
        cp_commit();                       // uniform; pairs with refills above

        const int nxt = cur ^ 1;
        if (owned) { sa0[nxt * PMAX + s] = la0; sa1[nxt * PMAX + s] = la1; }
        if (lane == 0) sE[nxt * NW + warp] = E;
    }

    // epilogue: per-batch loss
    __syncthreads();
    if (owned) { sa0[s] = la0; sa1[s] = la1; }
    if (lane == 0) sEf[warp] = E;
    __syncthreads();
    if (j == 0) {
        // owner warp of slot q: warp 0 owns 0..31; warp w>=1 owns 16w+16..16w+31
        int wx = (L <= 31) ? 0 : ((L >> 4) - 1);
        float v0 = sa0[L];
        float x = (v0 > 0.0f) ? (lg2f_(v0) + (float)sEf[wx]) : NEGF;
        float y = NEGF;
        if (L > 0) {
            int q = L - 1;
            int wy = (q <= 31) ? 0 : ((q >> 4) - 1);
            float v1 = sa1[q];
            if (v1 > 0.0f) y = lg2f_(v1) + (float)sEf[wy];
        }
        float ll2 = lae2(x, y);
        float loss = -ll2 * LN2;
        if (!(loss <= 1e29f)) loss = 0.0f;         // zero_infinity (+ nan/inf guard)
        int Lm = (L > 0) ? L : 1;
        g_loss[b] = loss / (float)Lm;
    }

    // fused deterministic reduction: last block sums in fixed order
    __threadfence();
    __syncthreads();
    if (j == 0) s_rank = atomicAdd(&g_ticket, 1u);
    __syncthreads();
    if (s_rank == (unsigned)(gridDim.x - 1)) {
        if (warp == 0) {
            float sum = 0.0f;
            for (int i = lane; i < B; i += 32) sum += g_loss[i];
            #pragma unroll
            for (int off = 16; off; off >>= 1)
                sum += __shfl_xor_sync(0xffffffffu, sum, off);
            if (lane == 0) {
                out[0] = sum / (float)B;
                g_ticket = 0;              // reset for next graph replay
            }
        }
    }
}

extern "C" void kernel_launch(void* const* d_in, const int* in_sizes, int n_in,
                              void* d_out, int out_size) {
    const float* log_probs = (const float*)d_in[0];
    const int*   in_len    = (const int*)d_in[1];
    const int*   targets   = (const int*)d_in[2];
    const int*   tgt_len   = (const int*)d_in[3];

    const int B = in_sizes[1];
    const int S = in_sizes[2] / B;
    const int V = 128;
    const int T = in_sizes[0] / (B * V);

    ctc_fwd_kernel<<<B, NT>>>(log_probs, in_len, targets, tgt_len,
                              (float*)d_out, T, V, S, B);
}